// round 10
// baseline (speedup 1.0000x reference)
// R10: byte-identical resubmit of R9 (pair-duplicated hbuf2 + reg-tail Wsm).
// Fourth broker flake; R5/R7/R8 precedent — real errors come with diagnostics.
#include <cuda_runtime.h>
#include <cuda_bf16.h>
#include <cstdint>
#include <math.h>

#define BATCH 512
#define TSTEPS 256
#define INPUT 512
#define HID 128
#define G4 512          // 4*HID
#define FC1DIM 64
#define NACT 10
#define MROWS (BATCH*TSTEPS)   // 131072

typedef unsigned long long u64t;

// ---------------- scratch (static device memory; no allocs) ----------------
__device__ float g_xproj[(size_t)MROWS * G4];        // 256 MB, reused by both layers
__device__ float g_Wt[2][HID * G4];                  // Whh transposed to [k][g]
__device__ __nv_bfloat16 g_x_hi[(size_t)MROWS * INPUT];   // 128 MB
__device__ __nv_bfloat16 g_x_lo[(size_t)MROWS * INPUT];   // 128 MB
__device__ __nv_bfloat16 g_h_hi[(size_t)MROWS * HID];     // 32 MB (layer0 h seq)
__device__ __nv_bfloat16 g_h_lo[(size_t)MROWS * HID];     // 32 MB
__device__ __nv_bfloat16 g_Wih0_hi[G4 * INPUT];
__device__ __nv_bfloat16 g_Wih0_lo[G4 * INPUT];
__device__ __nv_bfloat16 g_Wih1_hi[G4 * HID];
__device__ __nv_bfloat16 g_Wih1_lo[G4 * HID];

// output layout in d_out (float32):
//   probs [512*10]  | h_n [2*512*128] | c_n [2*512*128]
#define OUT_HN_OFF   (BATCH*NACT)                     // 5120
#define OUT_CN_OFF   (OUT_HN_OFF + 2*BATCH*HID)      // 136192

// ---------------- helpers ----------------
__device__ __forceinline__ float sigmoidf_(float x) {
    return 1.0f / (1.0f + __expf(-x));
}
__device__ __forceinline__ float tanhf_(float x) {
    return 1.0f - 2.0f / (__expf(2.0f * x) + 1.0f);
}
__device__ __forceinline__ uint32_t smem_u32(const void* p) {
    uint32_t a;
    asm("{ .reg .u64 t; cvta.to.shared.u64 t, %1; cvt.u32.u64 %0, t; }"
        : "=r"(a) : "l"(p));
    return a;
}
__device__ __forceinline__ uint32_t pack_bf16(float a, float b) {
    __nv_bfloat162 t = __floats2bfloat162_rn(a, b);
    return *reinterpret_cast<uint32_t*>(&t);
}
__device__ __forceinline__ void ldsm_x4(uint32_t& r0, uint32_t& r1,
                                        uint32_t& r2, uint32_t& r3,
                                        uint32_t addr) {
    asm volatile("ldmatrix.sync.aligned.m8n8.x4.shared.b16 {%0,%1,%2,%3}, [%4];"
                 : "=r"(r0), "=r"(r1), "=r"(r2), "=r"(r3) : "r"(addr));
}
__device__ __forceinline__ void mma16816(float* c, uint32_t a0, uint32_t a1,
                                         uint32_t a2, uint32_t a3,
                                         uint32_t b0, uint32_t b1) {
    asm volatile(
        "mma.sync.aligned.m16n8k16.row.col.f32.bf16.bf16.f32 "
        "{%0,%1,%2,%3}, {%4,%5,%6,%7}, {%8,%9}, {%0,%1,%2,%3};"
        : "+f"(c[0]), "+f"(c[1]), "+f"(c[2]), "+f"(c[3])
        : "r"(a0), "r"(a1), "r"(a2), "r"(a3), "r"(b0), "r"(b1));
}
// packed fp32x2 FMA (Blackwell; PTX ISA 8.6, target sm_100)
__device__ __forceinline__ void ffma2(u64t& acc, u64t a, u64t b) {
    asm("fma.rn.f32x2 %0, %1, %2, %0;" : "+l"(acc) : "l"(a), "l"(b));
}
__device__ __forceinline__ u64t bcast2(float x) {
    u64t r;
    asm("mov.b64 %0, {%1, %1};" : "=l"(r) : "f"(x));
    return r;
}
__device__ __forceinline__ float lo_f(u64t v) {
    return __uint_as_float((uint32_t)(v & 0xffffffffull));
}
__device__ __forceinline__ float hi_f(u64t v) {
    return __uint_as_float((uint32_t)(v >> 32));
}
__device__ __forceinline__ void cp_async16(uint32_t dst, const void* src) {
    asm volatile("cp.async.cg.shared.global [%0], [%1], 16;"
                 :: "r"(dst), "l"(src));
}
__device__ __forceinline__ void cp_commit() {
    asm volatile("cp.async.commit_group;");
}
template<int N>
__device__ __forceinline__ void cp_wait() {
    asm volatile("cp.async.wait_group %0;" :: "n"(N));
}

// ---------------- weight prep: transpose Whh + split Wih to bf16 hi/lo ----
__global__ void prep_weights_kernel(const float* __restrict__ whh0,
                                    const float* __restrict__ whh1,
                                    const float* __restrict__ wih0,
                                    const float* __restrict__ wih1) {
    int idx = blockIdx.x * 256 + threadIdx.x;   // up to 262144
    if (idx < 65536) {
        int k = idx >> 9;
        int g = idx & 511;
        g_Wt[0][k * G4 + g] = whh0[g * HID + k];
        g_Wt[1][k * G4 + g] = whh1[g * HID + k];
    }
    if (idx < G4 * INPUT) {
        float v = wih0[idx];
        __nv_bfloat16 h = __float2bfloat16(v);
        g_Wih0_hi[idx] = h;
        g_Wih0_lo[idx] = __float2bfloat16(v - __bfloat162float(h));
    }
    if (idx < G4 * HID) {
        float v = wih1[idx];
        __nv_bfloat16 h = __float2bfloat16(v);
        g_Wih1_hi[idx] = h;
        g_Wih1_lo[idx] = __float2bfloat16(v - __bfloat162float(h));
    }
}

// ---------------- split x into bf16 hi/lo (once) ----------------
__global__ void split_x_kernel(const float* __restrict__ x) {
    size_t i4 = (size_t)blockIdx.x * 256 + threadIdx.x;   // float4 index
    float4 v = *reinterpret_cast<const float4*>(&x[i4 * 4]);
    float hx = __bfloat162float(__float2bfloat16(v.x));
    float hy = __bfloat162float(__float2bfloat16(v.y));
    float hz = __bfloat162float(__float2bfloat16(v.z));
    float hw = __bfloat162float(__float2bfloat16(v.w));
    *reinterpret_cast<uint2*>(&g_x_hi[i4 * 4]) =
        make_uint2(pack_bf16(v.x, v.y), pack_bf16(v.z, v.w));
    *reinterpret_cast<uint2*>(&g_x_lo[i4 * 4]) =
        make_uint2(pack_bf16(v.x - hx, v.y - hy), pack_bf16(v.z - hz, v.w - hw));
}

// ---------------- mma.sync bf16 GEMM (cp.async double-buffered) ----------
#define SSTR 40
#define STG_ELEMS (4 * 128 * SSTR)   // 20480 bf16 per stage
#define T_AHI 0
#define T_ALO (128*SSTR)
#define T_WHI (2*128*SSTR)
#define T_WLO (3*128*SSTR)
#define GEMM_SMEM (2 * STG_ELEMS * 2)   // 81920 B

template<int K>
__global__ __launch_bounds__(256)
void gemm_mma_kernel(const __nv_bfloat16* __restrict__ Ahi,
                     const __nv_bfloat16* __restrict__ Alo,
                     const __nv_bfloat16* __restrict__ Whi,
                     const __nv_bfloat16* __restrict__ Wlo,
                     const float* __restrict__ bih,
                     const float* __restrict__ bhh,
                     float* __restrict__ C) {
    extern __shared__ __align__(16) __nv_bfloat16 smg[];

    const int tid = threadIdx.x;
    const int wid = tid >> 5;
    const int lane = tid & 31;
    const int wm = wid & 1;
    const int wn = wid >> 1;
    const int m0 = blockIdx.y * 128;
    const int n0 = blockIdx.x * 128;
    constexpr int NCH = K / 32;
    const uint32_t smb = smem_u32(smg);

    const int lr0 = tid >> 2;
    const int lc  = (tid & 3) * 8;

    auto load_stage = [&](int st, int kc) {
        uint32_t base = (uint32_t)(st * STG_ELEMS);
#pragma unroll
        for (int q = 0; q < 2; ++q) {
            int r = lr0 + q * 64;
            uint32_t so = base + r * SSTR + lc;
            cp_async16(smb + (so + T_AHI) * 2, &Ahi[(size_t)(m0 + r) * K + kc + lc]);
            cp_async16(smb + (so + T_ALO) * 2, &Alo[(size_t)(m0 + r) * K + kc + lc]);
            cp_async16(smb + (so + T_WHI) * 2, &Whi[(size_t)(n0 + r) * K + kc + lc]);
            cp_async16(smb + (so + T_WLO) * 2, &Wlo[(size_t)(n0 + r) * K + kc + lc]);
        }
    };

    float acc[4][4][4];
#pragma unroll
    for (int mf = 0; mf < 4; ++mf)
#pragma unroll
        for (int nf = 0; nf < 4; ++nf)
#pragma unroll
            for (int i = 0; i < 4; ++i) acc[mf][nf][i] = 0.0f;

    load_stage(0, 0);
    cp_commit();
    if (NCH > 1) load_stage(1, 32);
    cp_commit();

    const int a_row = (lane & 15);
    const int a_kofs = (lane >> 4) * 8;
    const int b_row = (lane & 7) + ((lane >> 4) & 1) * 8;
    const int b_kofs = ((lane >> 3) & 1) * 8;

    for (int ch = 0; ch < NCH; ++ch) {
        cp_wait<1>();
        __syncthreads();
        const uint32_t sb = smb + (uint32_t)((ch & 1) * STG_ELEMS) * 2;

#pragma unroll
        for (int kk = 0; kk < 32; kk += 16) {
            uint32_t bh[8], bl[8];
#pragma unroll
            for (int nfp = 0; nfp < 2; ++nfp) {
                int row = wn * 32 + nfp * 16 + b_row;
                uint32_t off = (uint32_t)(row * SSTR + kk + b_kofs) * 2;
                ldsm_x4(bh[nfp * 4 + 0], bh[nfp * 4 + 1],
                        bh[nfp * 4 + 2], bh[nfp * 4 + 3], sb + T_WHI * 2 + off);
                ldsm_x4(bl[nfp * 4 + 0], bl[nfp * 4 + 1],
                        bl[nfp * 4 + 2], bl[nfp * 4 + 3], sb + T_WLO * 2 + off);
            }
#pragma unroll
            for (int mf = 0; mf < 4; ++mf) {
                int row = wm * 64 + mf * 16 + a_row;
                uint32_t off = (uint32_t)(row * SSTR + kk + a_kofs) * 2;
                uint32_t ah0, ah1, ah2, ah3, al0, al1, al2, al3;
                ldsm_x4(ah0, ah1, ah2, ah3, sb + T_AHI * 2 + off);
                ldsm_x4(al0, al1, al2, al3, sb + T_ALO * 2 + off);
#pragma unroll
                for (int nf = 0; nf < 4; ++nf) {
                    uint32_t b0h = bh[(nf >> 1) * 4 + (nf & 1) * 2 + 0];
                    uint32_t b1h = bh[(nf >> 1) * 4 + (nf & 1) * 2 + 1];
                    uint32_t b0l = bl[(nf >> 1) * 4 + (nf & 1) * 2 + 0];
                    uint32_t b1l = bl[(nf >> 1) * 4 + (nf & 1) * 2 + 1];
                    mma16816(acc[mf][nf], ah0, ah1, ah2, ah3, b0h, b1h);
                    mma16816(acc[mf][nf], ah0, ah1, ah2, ah3, b0l, b1l);
                    mma16816(acc[mf][nf], al0, al1, al2, al3, b0h, b1h);
                }
            }
        }
        __syncthreads();
        if (ch + 2 < NCH) load_stage(ch & 1, (ch + 2) * 32);
        cp_commit();
    }

    const int mbase = m0 + wm * 64;
    const int nbase = n0 + wn * 32;
    float bs0[4], bs1[4];
#pragma unroll
    for (int nf = 0; nf < 4; ++nf) {
        int c = nbase + nf * 8 + (lane & 3) * 2;
        bs0[nf] = bih[c] + bhh[c];
        bs1[nf] = bih[c + 1] + bhh[c + 1];
    }
#pragma unroll
    for (int mf = 0; mf < 4; ++mf) {
        int row0 = mbase + mf * 16 + (lane >> 2);
#pragma unroll
        for (int nf = 0; nf < 4; ++nf) {
            int col = nbase + nf * 8 + (lane & 3) * 2;
            float2 v0 = make_float2(acc[mf][nf][0] + bs0[nf],
                                    acc[mf][nf][1] + bs1[nf]);
            float2 v1 = make_float2(acc[mf][nf][2] + bs0[nf],
                                    acc[mf][nf][3] + bs1[nf]);
            *reinterpret_cast<float2*>(&C[(size_t)row0 * G4 + col]) = v0;
            *reinterpret_cast<float2*>(&C[(size_t)(row0 + 8) * G4 + col]) = v1;
        }
    }
}

// ---------------- LSTM recurrence: ffma2, pair-duplicated h, reg tails ----
// smem: Wsm [4 slices][30 k][384 i,f,g gates] (k-rows 30,31 of each slice in
// regs) + part [16][128][4] + hbuf2 [4][128] duplicated (h,h) u64 pairs.
#define LSTM_WSM   (4*30*384)               // 46080 floats
#define LSTM_PART  (16*128*4)               // 8192 floats
#define LSTM_SMEM_FLOATS (LSTM_WSM + LSTM_PART + 4*128*2)   // 56320 fl = 225280 B

template<int LAYER>
__global__ __launch_bounds__(256, 1)
void lstm_kernel(const float* __restrict__ xproj,
                 float* __restrict__ out) {
    extern __shared__ float smemf[];
    float* Wsm  = smemf;                               // [4][30][384]
    float* part = smemf + LSTM_WSM;                    // [16][128][4]
    u64t* hbuf2 = reinterpret_cast<u64t*>(smemf + LSTM_WSM + LSTM_PART); // [4][128]

    const float* Wt = g_Wt[LAYER];            // [128][512]
    const int tid = threadIdx.x;
    const int b0 = blockIdx.x * 4;

    const int ksl  = tid >> 6;
    const int ggrp = tid & 63;
    const int k0   = ksl * 32;
    const int g2   = ggrp * 2;

    // stage i,f,g weights for k-rows 0..29 of each slice
    for (int i = tid; i < 4 * 30 * 96; i += 256) {
        int s = i / (30 * 96);
        int rem = i - s * 30 * 96;
        int kk = rem / 96;
        int gc4 = (rem % 96) * 4;
        *(float4*)&Wsm[(s * 30 + kk) * 384 + gc4] =
            *(const float4*)&Wt[(size_t)(s * 32 + kk) * G4 + gc4];
    }
    for (int i = tid; i < 4 * 128; i += 256) hbuf2[i] = 0ull;
    float creg[2] = {0.0f, 0.0f};

    // register-resident weights: o-gate pairs for all 32 k, i/f/g for k 30,31
    u64t wo[32];
#pragma unroll
    for (int kk = 0; kk < 32; ++kk)
        wo[kk] = *(const u64t*)&Wt[(size_t)(k0 + kk) * G4 + 384 + g2];
    u64t wtl[2][3];
#pragma unroll
    for (int j = 0; j < 2; ++j)
#pragma unroll
        for (int c = 0; c < 3; ++c)
            wtl[j][c] = *(const u64t*)&Wt[(size_t)(k0 + 30 + j) * G4 + c * 128 + g2];

    __syncthreads();

    for (int t = 0; t < TSTEPS; ++t) {
        float xv[2][4];
#pragma unroll
        for (int cc = 0; cc < 2; ++cc) {
            int cell = tid + cc * 256;
            int r = cell >> 7, hc = cell & 127;
            const float* xp = xproj + ((size_t)(b0 + r) * TSTEPS + t) * G4 + hc;
            xv[cc][0] = xp[0];   xv[cc][1] = xp[128];
            xv[cc][2] = xp[256]; xv[cc][3] = xp[384];
        }

        u64t acc2[4][4];
#pragma unroll
        for (int r = 0; r < 4; ++r)
#pragma unroll
            for (int jp = 0; jp < 4; ++jp) acc2[r][jp] = 0ull;

        // k-pairs 0..14: weights from smem
#pragma unroll
        for (int kp = 0; kp < 15; ++kp) {
            const int kk = kp * 2;
            const int k = k0 + kk;
            ulonglong2 hv[4];
#pragma unroll
            for (int r = 0; r < 4; ++r)
                hv[r] = *reinterpret_cast<const ulonglong2*>(&hbuf2[r * 128 + k]);
            const float* wpa = &Wsm[(ksl * 30 + kk) * 384];
            const float* wpb = wpa + 384;
            u64t w0a = *(const u64t*)&wpa[g2];
            u64t w1a = *(const u64t*)&wpa[128 + g2];
            u64t w2a = *(const u64t*)&wpa[256 + g2];
            u64t w0b = *(const u64t*)&wpb[g2];
            u64t w1b = *(const u64t*)&wpb[128 + g2];
            u64t w2b = *(const u64t*)&wpb[256 + g2];
#pragma unroll
            for (int r = 0; r < 4; ++r) {
                ffma2(acc2[r][0], hv[r].x, w0a);
                ffma2(acc2[r][1], hv[r].x, w1a);
                ffma2(acc2[r][2], hv[r].x, w2a);
                ffma2(acc2[r][3], hv[r].x, wo[kk]);
                ffma2(acc2[r][0], hv[r].y, w0b);
                ffma2(acc2[r][1], hv[r].y, w1b);
                ffma2(acc2[r][2], hv[r].y, w2b);
                ffma2(acc2[r][3], hv[r].y, wo[kk + 1]);
            }
        }
        // k-pair 15 (k 30,31): weights from registers
        {
            const int k = k0 + 30;
            ulonglong2 hv[4];
#pragma unroll
            for (int r = 0; r < 4; ++r)
                hv[r] = *reinterpret_cast<const ulonglong2*>(&hbuf2[r * 128 + k]);
#pragma unroll
            for (int r = 0; r < 4; ++r) {
                ffma2(acc2[r][0], hv[r].x, wtl[0][0]);
                ffma2(acc2[r][1], hv[r].x, wtl[0][1]);
                ffma2(acc2[r][2], hv[r].x, wtl[0][2]);
                ffma2(acc2[r][3], hv[r].x, wo[30]);
                ffma2(acc2[r][0], hv[r].y, wtl[1][0]);
                ffma2(acc2[r][1], hv[r].y, wtl[1][1]);
                ffma2(acc2[r][2], hv[r].y, wtl[1][2]);
                ffma2(acc2[r][3], hv[r].y, wo[31]);
            }
        }

        // transposed partial store: part[(ksl*4+r)*128 + hc][0..3] via STS.128
#pragma unroll
        for (int r = 0; r < 4; ++r) {
            float4 lo4 = make_float4(lo_f(acc2[r][0]), lo_f(acc2[r][1]),
                                     lo_f(acc2[r][2]), lo_f(acc2[r][3]));
            float4 hi4 = make_float4(hi_f(acc2[r][0]), hi_f(acc2[r][1]),
                                     hi_f(acc2[r][2]), hi_f(acc2[r][3]));
            float* pb = &part[(size_t)((ksl * 4 + r) * 128 + g2) * 4];
            *reinterpret_cast<float4*>(pb) = lo4;
            *reinterpret_cast<float4*>(pb + 4) = hi4;
        }
        __syncthreads();

#pragma unroll
        for (int cc = 0; cc < 2; ++cc) {
            int cell = tid + cc * 256;
            int r = cell >> 7, hc = cell & 127;
            float4 p0 = *reinterpret_cast<const float4*>(
                &part[(size_t)((0 * 4 + r) * 128 + hc) * 4]);
            float4 p1 = *reinterpret_cast<const float4*>(
                &part[(size_t)((1 * 4 + r) * 128 + hc) * 4]);
            float4 p2 = *reinterpret_cast<const float4*>(
                &part[(size_t)((2 * 4 + r) * 128 + hc) * 4]);
            float4 p3 = *reinterpret_cast<const float4*>(
                &part[(size_t)((3 * 4 + r) * 128 + hc) * 4]);
            float gi = xv[cc][0] + p0.x + p1.x + p2.x + p3.x;
            float gf = xv[cc][1] + p0.y + p1.y + p2.y + p3.y;
            float gg = xv[cc][2] + p0.z + p1.z + p2.z + p3.z;
            float go = xv[cc][3] + p0.w + p1.w + p2.w + p3.w;
            float iv = sigmoidf_(gi);
            float fv = sigmoidf_(gf);
            float gv = tanhf_(gg);
            float ov = sigmoidf_(go);
            float c = fv * creg[cc] + iv * gv;
            creg[cc] = c;
            float h = ov * tanhf_(c);
            hbuf2[r * 128 + hc] = bcast2(h);
            if (LAYER == 0) {
                size_t o = ((size_t)(b0 + r) * TSTEPS + t) * HID + hc;
                __nv_bfloat16 hb = __float2bfloat16(h);
                g_h_hi[o] = hb;
                g_h_lo[o] = __float2bfloat16(h - __bfloat162float(hb));
            }
        }
        __syncthreads();
    }

#pragma unroll
    for (int cc = 0; cc < 2; ++cc) {
        int cell = tid + cc * 256;
        int r = cell >> 7, hc = cell & 127;
        int bi = b0 + r;
        out[OUT_HN_OFF + LAYER * BATCH * HID + bi * HID + hc] = lo_f(hbuf2[r * 128 + hc]);
        out[OUT_CN_OFF + LAYER * BATCH * HID + bi * HID + hc] = creg[cc];
    }
}

// ---------------- head: relu(h@fc1^T+b1)@fc2^T+b2 -> softmax ----------------
__global__ __launch_bounds__(256)
void head_kernel(const float* __restrict__ fc1w, const float* __restrict__ fc1b,
                 const float* __restrict__ fc2w, const float* __restrict__ fc2b,
                 float* __restrict__ out) {
    __shared__ float sw1[FC1DIM * HID];
    __shared__ float sw2[NACT * FC1DIM];
    __shared__ float sb1[FC1DIM];
    __shared__ float sb2[NACT];

    for (int i = threadIdx.x; i < FC1DIM * HID; i += 256) sw1[i] = fc1w[i];
    for (int i = threadIdx.x; i < NACT * FC1DIM; i += 256) sw2[i] = fc2w[i];
    if (threadIdx.x < FC1DIM) sb1[threadIdx.x] = fc1b[threadIdx.x];
    if (threadIdx.x < NACT) sb2[threadIdx.x] = fc2b[threadIdx.x];
    __syncthreads();

    int row = blockIdx.x * 256 + threadIdx.x;
    const float* h = out + OUT_HN_OFF + BATCH * HID + row * HID;

    float hid[FC1DIM];
#pragma unroll
    for (int j = 0; j < FC1DIM; ++j) hid[j] = sb1[j];
    for (int k = 0; k < HID; ++k) {
        float hv = h[k];
#pragma unroll
        for (int j = 0; j < FC1DIM; ++j)
            hid[j] += hv * sw1[j * HID + k];
    }
#pragma unroll
    for (int j = 0; j < FC1DIM; ++j) hid[j] = fmaxf(hid[j], 0.0f);

    float logit[NACT];
    float mx = -1e30f;
#pragma unroll
    for (int a = 0; a < NACT; ++a) {
        float l = sb2[a];
#pragma unroll
        for (int j = 0; j < FC1DIM; ++j)
            l += hid[j] * sw2[a * FC1DIM + j];
        logit[a] = l;
        mx = fmaxf(mx, l);
    }
    float sum = 0.0f;
#pragma unroll
    for (int a = 0; a < NACT; ++a) {
        logit[a] = __expf(logit[a] - mx);
        sum += logit[a];
    }
    float inv = 1.0f / sum;
#pragma unroll
    for (int a = 0; a < NACT; ++a)
        out[row * NACT + a] = logit[a] * inv;
}

// ---------------- launch ----------------
extern "C" void kernel_launch(void* const* d_in, const int* in_sizes, int n_in,
                              void* d_out, int out_size) {
    (void)in_sizes; (void)n_in; (void)out_size;
    const float* x     = (const float*)d_in[0];
    const float* Wih0  = (const float*)d_in[1];
    const float* Whh0  = (const float*)d_in[2];
    const float* bih0  = (const float*)d_in[3];
    const float* bhh0  = (const float*)d_in[4];
    const float* Wih1  = (const float*)d_in[5];
    const float* Whh1  = (const float*)d_in[6];
    const float* bih1  = (const float*)d_in[7];
    const float* bhh1  = (const float*)d_in[8];
    const float* fc1w  = (const float*)d_in[9];
    const float* fc1b  = (const float*)d_in[10];
    const float* fc2w  = (const float*)d_in[11];
    const float* fc2b  = (const float*)d_in[12];
    float* out = (float*)d_out;

    float* xproj = nullptr;
    __nv_bfloat16 *xhi, *xlo, *hhi, *hlo, *w0hi, *w0lo, *w1hi, *w1lo;
    cudaGetSymbolAddress((void**)&xproj, g_xproj);
    cudaGetSymbolAddress((void**)&xhi, g_x_hi);
    cudaGetSymbolAddress((void**)&xlo, g_x_lo);
    cudaGetSymbolAddress((void**)&hhi, g_h_hi);
    cudaGetSymbolAddress((void**)&hlo, g_h_lo);
    cudaGetSymbolAddress((void**)&w0hi, g_Wih0_hi);
    cudaGetSymbolAddress((void**)&w0lo, g_Wih0_lo);
    cudaGetSymbolAddress((void**)&w1hi, g_Wih1_hi);
    cudaGetSymbolAddress((void**)&w1lo, g_Wih1_lo);

    cudaFuncSetAttribute(lstm_kernel<0>,
                         cudaFuncAttributeMaxDynamicSharedMemorySize,
                         LSTM_SMEM_FLOATS * 4);
    cudaFuncSetAttribute(lstm_kernel<1>,
                         cudaFuncAttributeMaxDynamicSharedMemorySize,
                         LSTM_SMEM_FLOATS * 4);
    cudaFuncSetAttribute(gemm_mma_kernel<INPUT>,
                         cudaFuncAttributeMaxDynamicSharedMemorySize, GEMM_SMEM);
    cudaFuncSetAttribute(gemm_mma_kernel<HID>,
                         cudaFuncAttributeMaxDynamicSharedMemorySize, GEMM_SMEM);

    // 1) weight prep + x split
    prep_weights_kernel<<<1024, 256>>>(Whh0, Whh1, Wih0, Wih1);
    split_x_kernel<<<MROWS * INPUT / 4 / 256, 256>>>(x);

    // 2) x_proj0 = x @ Wih0^T + bias (tensor cores, double-buffered)
    gemm_mma_kernel<INPUT><<<dim3(4, MROWS / 128), 256, GEMM_SMEM>>>(
        xhi, xlo, w0hi, w0lo, bih0, bhh0, xproj);

    // 3) layer-0 recurrence (writes h seq as bf16 hi/lo)
    lstm_kernel<0><<<BATCH / 4, 256, LSTM_SMEM_FLOATS * 4>>>(xproj, out);

    // 4) x_proj1 = h0_seq @ Wih1^T + bias
    gemm_mma_kernel<HID><<<dim3(4, MROWS / 128), 256, GEMM_SMEM>>>(
        hhi, hlo, w1hi, w1lo, bih1, bhh1, xproj);

    // 5) layer-1 recurrence
    lstm_kernel<1><<<BATCH / 4, 256, LSTM_SMEM_FLOATS * 4>>>(xproj, out);

    // 6) head
    head_kernel<<<2, 256>>>(fc1w, fc1b, fc2w, fc2b, out);
}